// round 12
// baseline (speedup 1.0000x reference)
#include <cuda_runtime.h>
#include <cuda_bf16.h>
#include <cuda_fp8.h>
#include <cstdint>

// Problem constants
#define KROWS 2048          // N*BS = 16*128
#define DDIM 4096
#define NTILE 16            // num_transforms, also number of 128-col tiles
#define SLAB 1572864        // BS*C*H*W floats per transform slab
#define PIC_ELEMS 25165824  // N*BS*C*H*W

#define NB_GEMM 136
#define NB_MSE 160
#define NB_TOTAL (NB_GEMM + NB_MSE)  // 296 = 2 blocks x 148 SMs

// Scratch (static device globals; no runtime allocation)
__device__ uint8_t g_sn8[(size_t)KROWS * DDIM];  // normalized h * 64, e4m3 (8 MB)
__device__ float g_Epart[KROWS * 16];            // [row][tile] exp row sums
__device__ float g_P[KROWS * 16];                // same-mod sims (incl diag)
__device__ float g_msepart[NB_MSE];
__device__ float g_losspart[NB_GEMM];

// Monotonic grid-sync counters (generation arithmetic — never reset, so
// graph replays work; counter state does not affect output).
__device__ unsigned g_c1, g_c2, g_c3, g_cmse;

// ---------------------------------------------------------------------------
#define LDSS8 144                    // smem row stride bytes (128 + 16 pad)
#define TILE8 (128 * LDSS8)          // 18432 bytes per tile buffer
#define STAGEB (2 * TILE8)           // A+B per stage = 36864
#define STAGES 3
#define SMEM_TC (STAGES * STAGEB)    // 110592 bytes

__device__ __forceinline__ uint32_t smem_u32(const void* p) {
    return (uint32_t)__cvta_generic_to_shared(p);
}

__device__ __forceinline__ void cp_async16(uint32_t s, const void* g) {
    asm volatile("cp.async.cg.shared.global [%0], [%1], 16;\n" :: "r"(s), "l"(g));
}

__device__ __forceinline__ void ldsm4(uint32_t& r0, uint32_t& r1, uint32_t& r2,
                                      uint32_t& r3, uint32_t a) {
    asm volatile("ldmatrix.sync.aligned.m8n8.x4.shared.b16 {%0,%1,%2,%3}, [%4];\n"
                 : "=r"(r0), "=r"(r1), "=r"(r2), "=r"(r3)
                 : "r"(a));
}

__device__ __forceinline__ void mma16832(float c[4], const uint32_t a[4],
                                         const uint32_t b[2]) {
    asm volatile(
        "mma.sync.aligned.m16n8k32.row.col.f32.e4m3.e4m3.f32 "
        "{%0,%1,%2,%3}, {%4,%5,%6,%7}, {%8,%9}, {%0,%1,%2,%3};\n"
        : "+f"(c[0]), "+f"(c[1]), "+f"(c[2]), "+f"(c[3])
        : "r"(a[0]), "r"(a[1]), "r"(a[2]), "r"(a[3]), "r"(b[0]), "r"(b[1]));
}

// Grid barrier among the NB_GEMM gemm blocks (bids 0..135 — all first-wave
// resident at any occupancy, so spinning is deadlock-free). Generation-based:
// no reset needed across graph replays.
__device__ __forceinline__ void grid_bar(unsigned* ctr) {
    __threadfence();     // publish this thread's prior writes
    __syncthreads();
    if (threadIdx.x == 0) {
        const unsigned ticket = atomicAdd(ctr, 1u);
        const unsigned target = (ticket / NB_GEMM + 1u) * NB_GEMM;
        while (atomicAdd(ctr, 0u) < target) {}
    }
    __syncthreads();
    __threadfence();     // acquire for subsequent reads
}

__global__ void __launch_bounds__(256, 2) k_all(const float* __restrict__ pic,
                                                const float* __restrict__ dec,
                                                const float* __restrict__ h,
                                                float* __restrict__ out) {
    extern __shared__ char smem[];
    const int tid = threadIdx.x;
    __shared__ float wred[8];
    __shared__ float wred2[8];
    __shared__ float s_bcast;
    __shared__ unsigned s_t3;

    if (blockIdx.x >= NB_GEMM) {
        // ---------------- MSE branch (starts immediately, runs under gemm) --
        const int mb = blockIdx.x - NB_GEMM;
        const int total4 = PIC_ELEMS / 4;
        const int slab4 = SLAB / 4;
        float s = 0.f;
        for (int i4 = mb * 256 + tid; i4 < total4; i4 += NB_MSE * 256) {
            const int n = i4 / slab4;
            const int rem4 = i4 - n * slab4;
            const int di4 = ((n + 1) & 15) * slab4 + rem4;
            const float4 a = *((const float4*)pic + i4);
            const float4 b = *((const float4*)dec + di4);
            const float dx = a.x - b.x, dy = a.y - b.y, dz = a.z - b.z,
                        dw = a.w - b.w;
            s += dx * dx + dy * dy + dz * dz + dw * dw;
        }
        const int lane = tid & 31, warp = tid >> 5;
#pragma unroll
        for (int o = 16; o > 0; o >>= 1) s += __shfl_xor_sync(0xffffffffu, s, o);
        if (lane == 0) wred[warp] = s;
        __syncthreads();
        if (tid == 0) {
            float t = 0.f;
#pragma unroll
            for (int i = 0; i < 8; i++) t += wred[i];
            g_msepart[mb] = t;
            __threadfence();
            atomicAdd(&g_cmse, 1u);
        }
        return;
    }

    // ---------------- GEMM block: norm slice -> barrier -> gemm -> loss ----
    const int b = blockIdx.x;
    const int lane = tid & 31, warp = tid >> 5;

    // Row slice for norm + loss phases: 136 blocks cover 2048 rows.
    const int rbase = b * 15 + (b < 8 ? b : 8);
    const int rcnt = 15 + (b < 8 ? 1 : 0);

    // ---- Phase 0: normalize rows [rbase, rbase+rcnt), write e4m3*64 ----
    {
        float4 v[4], vn[4];
        {
            const float4* src = (const float4*)(h + (size_t)rbase * DDIM);
#pragma unroll
            for (int i = 0; i < 4; i++) v[i] = src[tid * 4 + i];
        }
        for (int r = 0; r < rcnt; r++) {
            if (r + 1 < rcnt) {  // prefetch next row (hides DRAM latency)
                const float4* src =
                    (const float4*)(h + (size_t)(rbase + r + 1) * DDIM);
#pragma unroll
                for (int i = 0; i < 4; i++) vn[i] = src[tid * 4 + i];
            }
            float s = 0.f;
#pragma unroll
            for (int i = 0; i < 4; i++)
                s += v[i].x * v[i].x + v[i].y * v[i].y + v[i].z * v[i].z +
                     v[i].w * v[i].w;
#pragma unroll
            for (int o = 16; o > 0; o >>= 1)
                s += __shfl_xor_sync(0xffffffffu, s, o);
            if (lane == 0) wred[warp] = s;
            __syncthreads();
            if (tid == 0) {
                float t = 0.f;
#pragma unroll
                for (int i = 0; i < 8; i++) t += wred[i];
                s_bcast = 64.f / fmaxf(sqrtf(t), 1e-8f);
            }
            __syncthreads();
            const float inv = s_bcast;
            uint32_t packed[4];
#pragma unroll
            for (int i = 0; i < 4; i++) {
                float2 lo = make_float2(v[i].x * inv, v[i].y * inv);
                float2 hi = make_float2(v[i].z * inv, v[i].w * inv);
                const uint32_t plo =
                    __nv_cvt_float2_to_fp8x2(lo, __NV_SATFINITE, __NV_E4M3);
                const uint32_t phi =
                    __nv_cvt_float2_to_fp8x2(hi, __NV_SATFINITE, __NV_E4M3);
                packed[i] = (plo & 0xFFFFu) | (phi << 16);
            }
            uint4 u;
            u.x = packed[0]; u.y = packed[1]; u.z = packed[2]; u.w = packed[3];
            *(uint4*)(g_sn8 + (size_t)(rbase + r) * DDIM + tid * 16) = u;
#pragma unroll
            for (int i = 0; i < 4; i++) v[i] = vn[i];
            __syncthreads();  // wred reuse safety
        }
    }

    // ---- Barrier 1: all of g_sn8 written ----
    grid_bar(&g_c1);

    // ---- Phase 1: FP8 GEMM tile ----
    const int wm = warp >> 2, wn = warp & 3;
    int bidx = b, tm = 0;
    while (bidx >= 16 - tm) { bidx -= 16 - tm; tm++; }
    const int tn = tm + bidx;
    const int mbase = tm * 128, nbase = tn * 128;

    float acc[4][4][4];
#pragma unroll
    for (int i = 0; i < 4; i++)
#pragma unroll
        for (int j = 0; j < 4; j++)
#pragma unroll
            for (int k = 0; k < 4; k++) acc[i][j][k] = 0.f;

    auto load_chunk = [&](int c, int stg) {
        const uint32_t sa = smem_u32(smem + stg * STAGEB);
        const uint32_t sbm = sa + TILE8;
#pragma unroll
        for (int i = 0; i < 4; i++) {
            const int idx = tid + i * 256;  // 0..1023
            const int row = idx >> 3;       // 0..127
            const int c16 = idx & 7;        // 16B chunk within 128B row
            const uint32_t so = (uint32_t)(row * LDSS8 + c16 * 16);
            cp_async16(sa + so,
                       g_sn8 + (size_t)(mbase + row) * DDIM + (c << 7) + c16 * 16);
            cp_async16(sbm + so,
                       g_sn8 + (size_t)(nbase + row) * DDIM + (c << 7) + c16 * 16);
        }
        asm volatile("cp.async.commit_group;\n" ::: "memory");
    };

    const int a_row_off = ((lane >> 3) & 1) * 8 + (lane & 7);
    const int a_col_off = ((lane >> 4) & 1) * 16;  // bytes
    const int b_grp = lane >> 3;
    const int b_row_off = (b_grp >> 1) * 8 + (lane & 7);
    const int b_col_off = (b_grp & 1) * 16;        // bytes

    load_chunk(0, 0);
    load_chunk(1, 1);

    for (int c = 0; c < 32; c++) {
        const int stg = c % STAGES;
        if (c < 31) {
            asm volatile("cp.async.wait_group 1;\n" ::: "memory");
        } else {
            asm volatile("cp.async.wait_group 0;\n" ::: "memory");
        }
        __syncthreads();
        if (c + 2 < 32) load_chunk(c + 2, (c + 2) % STAGES);

        const char* As = smem + stg * STAGEB;
        const char* Bs = smem + stg * STAGEB + TILE8;
#pragma unroll
        for (int ksb = 0; ksb < 128; ksb += 32) {
            uint32_t a[4][4], bb[4][2];
#pragma unroll
            for (int mi = 0; mi < 4; mi++) {
                const uint32_t ad = smem_u32(
                    As + (wm * 64 + mi * 16 + a_row_off) * LDSS8 + ksb + a_col_off);
                ldsm4(a[mi][0], a[mi][1], a[mi][2], a[mi][3], ad);
            }
#pragma unroll
            for (int nb = 0; nb < 2; nb++) {
                const uint32_t ad = smem_u32(
                    Bs + (wn * 32 + nb * 16 + b_row_off) * LDSS8 + ksb + b_col_off);
                uint32_t r0, r1, r2, r3;
                ldsm4(r0, r1, r2, r3, ad);
                bb[nb * 2][0] = r0;
                bb[nb * 2][1] = r1;
                bb[nb * 2 + 1][0] = r2;
                bb[nb * 2 + 1][1] = r3;
            }
#pragma unroll
            for (int mi = 0; mi < 4; mi++)
#pragma unroll
                for (int ni = 0; ni < 4; ni++) mma16832(acc[mi][ni], a[mi], bb[ni]);
        }
    }
    __syncthreads();

    // ---- Epilogue: exp sums + diagonal capture ----
    const float LGSCALE = 1.f / 2048.f;   // acc holds 4096*sim; logit=acc/2048
    const float SIMSCALE = 1.f / 4096.f;
    float* redbuf = (float*)smem;         // 128 rows x 4 wn-warps
    float* colbuf = (float*)smem + 512;   // 128 cols x 2 wm-warps
    const int quad = lane >> 2, tid4 = lane & 3;

    float cs0[4], cs1[4];
#pragma unroll
    for (int ni = 0; ni < 4; ni++) { cs0[ni] = 0.f; cs1[ni] = 0.f; }

#pragma unroll
    for (int mi = 0; mi < 4; mi++) {
        float s0 = 0.f, s1 = 0.f;
        const int r0l = wm * 64 + mi * 16 + quad;
#pragma unroll
        for (int ni = 0; ni < 4; ni++) {
            const int c0l = wn * 32 + ni * 8 + tid4 * 2;
            const float v0 = acc[mi][ni][0], v1 = acc[mi][ni][1];
            const float v2 = acc[mi][ni][2], v3 = acc[mi][ni][3];
            const float e0 = __expf(LGSCALE * v0), e1 = __expf(LGSCALE * v1);
            const float e2 = __expf(LGSCALE * v2), e3 = __expf(LGSCALE * v3);
            s0 += e0 + e1;
            s1 += e2 + e3;
            cs0[ni] += e0 + e2;
            cs1[ni] += e1 + e3;
            if (r0l == c0l) {
                g_P[(size_t)(mbase + r0l) * 16 + tn] = v0 * SIMSCALE;
                if (tm != tn) g_P[(size_t)(nbase + c0l) * 16 + tm] = v0 * SIMSCALE;
            }
            if (r0l == c0l + 1) {
                g_P[(size_t)(mbase + r0l) * 16 + tn] = v1 * SIMSCALE;
                if (tm != tn) g_P[(size_t)(nbase + c0l + 1) * 16 + tm] = v1 * SIMSCALE;
            }
            if (r0l + 8 == c0l) {
                g_P[(size_t)(mbase + r0l + 8) * 16 + tn] = v2 * SIMSCALE;
                if (tm != tn) g_P[(size_t)(nbase + c0l) * 16 + tm] = v2 * SIMSCALE;
            }
            if (r0l + 8 == c0l + 1) {
                g_P[(size_t)(mbase + r0l + 8) * 16 + tn] = v3 * SIMSCALE;
                if (tm != tn) g_P[(size_t)(nbase + c0l + 1) * 16 + tm] = v3 * SIMSCALE;
            }
        }
        s0 += __shfl_xor_sync(0xffffffffu, s0, 1);
        s0 += __shfl_xor_sync(0xffffffffu, s0, 2);
        s1 += __shfl_xor_sync(0xffffffffu, s1, 1);
        s1 += __shfl_xor_sync(0xffffffffu, s1, 2);
        if (tid4 == 0) {
            redbuf[r0l * 4 + wn] = s0;
            redbuf[(r0l + 8) * 4 + wn] = s1;
        }
    }
#pragma unroll
    for (int ni = 0; ni < 4; ni++) {
#pragma unroll
        for (int o = 4; o < 32; o <<= 1) {
            cs0[ni] += __shfl_xor_sync(0xffffffffu, cs0[ni], o);
            cs1[ni] += __shfl_xor_sync(0xffffffffu, cs1[ni], o);
        }
        if (lane < 4) {
            const int col = wn * 32 + ni * 8 + lane * 2;
            colbuf[col * 2 + wm] = cs0[ni];
            colbuf[(col + 1) * 2 + wm] = cs1[ni];
        }
    }
    __syncthreads();
    if (tid < 128) {
        const float t = redbuf[tid * 4 + 0] + redbuf[tid * 4 + 1] +
                        redbuf[tid * 4 + 2] + redbuf[tid * 4 + 3];
        g_Epart[(size_t)(mbase + tid) * 16 + tn] = t;
        if (tm != tn) {
            const float cst = colbuf[tid * 2 + 0] + colbuf[tid * 2 + 1];
            g_Epart[(size_t)(nbase + tid) * 16 + tm] = cst;
        }
    }

    // ---- Barrier 2: all Epart/P written ----
    grid_bar(&g_c2);

    // ---- Phase 2: per-row loss partials for this block's row slice ----
    float contrib = 0.f;
    if (tid < rcnt) {
        const int i = rbase + tid;
        const int nrow = i >> 7;
        float4 ep[4], pp[4];
#pragma unroll
        for (int q = 0; q < 4; q++) {
            ep[q] = *((const float4*)(g_Epart + i * 16) + q);
            pp[q] = *((const float4*)(g_P + i * 16) + q);
        }
        const float* epf = (const float*)ep;
        const float* ppf = (const float*)pp;
        float esum = 0.f, esub = 0.f;
        float pv[16], ev[16];
#pragma unroll
        for (int m = 0; m < 16; m++) {
            esum += epf[m];
            pv[m] = 2.f * ppf[m];
            ev[m] = __expf(pv[m]);
            esub += ev[m];
        }
        const float eneg = esum - esub;
#pragma unroll
        for (int m = 0; m < 16; m++)
            if (m != nrow) contrib += __logf(eneg + ev[m]) - pv[m];
    }
    if (tid < 32) {
#pragma unroll
        for (int o = 16; o > 0; o >>= 1)
            contrib += __shfl_xor_sync(0xffffffffu, contrib, o);
        if (tid == 0) g_losspart[b] = contrib;
    }
    __syncthreads();

    // ---- Final combine: last gemm block to arrive joins mse and writes out.
    if (tid == 0) {
        __threadfence();
        s_t3 = atomicAdd(&g_c3, 1u);
    }
    __syncthreads();
    const unsigned t3 = s_t3;
    if ((t3 % NB_GEMM) == NB_GEMM - 1) {
        const unsigned gen = t3 / NB_GEMM;
        if (tid == 0) {
            while (atomicAdd(&g_cmse, 0u) < (gen + 1u) * NB_MSE) {}
            __threadfence();
        }
        __syncthreads();
        float sl = (tid < NB_GEMM) ? g_losspart[tid] : 0.f;
        float sm = (tid < NB_MSE) ? g_msepart[tid] : 0.f;
#pragma unroll
        for (int o = 16; o > 0; o >>= 1) {
            sl += __shfl_xor_sync(0xffffffffu, sl, o);
            sm += __shfl_xor_sync(0xffffffffu, sm, o);
        }
        if (lane == 0) { wred[warp] = sl; wred2[warp] = sm; }
        __syncthreads();
        if (tid == 0) {
            float lt = 0.f, mt = 0.f;
#pragma unroll
            for (int j = 0; j < 8; j++) { lt += wred[j]; mt += wred2[j]; }
            out[0] = mt * (1.f / (float)PIC_ELEMS) +
                     lt * (1.f / (float)(KROWS * 15));
        }
    }
}

// ---------------------------------------------------------------------------
extern "C" void kernel_launch(void* const* d_in, const int* in_sizes, int n_in,
                              void* d_out, int out_size) {
    (void)in_sizes; (void)n_in; (void)out_size;
    const float* pic = (const float*)d_in[0];
    const float* dec = (const float*)d_in[1];
    const float* h   = (const float*)d_in[2];

    // Idempotent host-side attribute set (no device memory, no stream work).
    cudaFuncSetAttribute(k_all, cudaFuncAttributeMaxDynamicSharedMemorySize,
                         SMEM_TC);

    k_all<<<NB_TOTAL, 256, SMEM_TC>>>(pic, dec, h, (float*)d_out);
}

// round 13
// speedup vs baseline: 1.1214x; 1.1214x over previous
#include <cuda_runtime.h>
#include <cuda_bf16.h>
#include <cuda_fp8.h>
#include <cstdint>

// Problem constants
#define KROWS 2048          // N*BS = 16*128
#define DDIM 4096
#define NTILE 16            // num_transforms, also number of 128-col tiles
#define SLAB 1572864        // BS*C*H*W floats per transform slab
#define PIC_ELEMS 25165824  // N*BS*C*H*W

#define NB_GEMM 136
#define NB_MSE 160
#define NB_TOTAL (NB_GEMM + NB_MSE)  // 296 = 2 blocks x 148 SMs

// Scratch (static device globals; no runtime allocation)
__device__ uint8_t g_sn8[(size_t)KROWS * DDIM];  // normalized h * 64, e4m3 (8 MB)
__device__ float g_Epart[KROWS * 16];            // [row][tile] exp row sums
__device__ float g_P[KROWS * 16];                // same-mod sims (incl diag)
__device__ float g_msepart[NB_MSE];
__device__ float g_losspart[NB_GEMM];

// Monotonic sync counters (generation arithmetic — never reset, so graph
// replays work; counter state does not affect output).
__device__ unsigned g_c2, g_c3, g_cmse;

// ---------------------------------------------------------------------------
// Kernel 1: row L2 norms of h, write (sn * 64) as e4m3.  2048 blocks — keeps
// the norm fully parallel (folding it into the 136 gemm blocks regressed).
// ---------------------------------------------------------------------------
__global__ void k_norm(const float* __restrict__ h) {
    const int row = blockIdx.x;
    const int tid = threadIdx.x;
    const float4* src = (const float4*)(h + (size_t)row * DDIM);

    float4 v[4];
    float s = 0.f;
#pragma unroll
    for (int i = 0; i < 4; i++) {
        v[i] = src[tid * 4 + i];
        s += v[i].x * v[i].x + v[i].y * v[i].y + v[i].z * v[i].z + v[i].w * v[i].w;
    }

    __shared__ float wred[8];
    __shared__ float s_inv;
    const int lane = tid & 31, warp = tid >> 5;
#pragma unroll
    for (int o = 16; o > 0; o >>= 1) s += __shfl_xor_sync(0xffffffffu, s, o);
    if (lane == 0) wred[warp] = s;
    __syncthreads();
    if (tid == 0) {
        float t = 0.f;
#pragma unroll
        for (int i = 0; i < 8; i++) t += wred[i];
        s_inv = 64.f / fmaxf(sqrtf(t), 1e-8f);  // fp8 pre-scale folded in
    }
    __syncthreads();
    const float inv = s_inv;

    uint32_t packed[4];
#pragma unroll
    for (int i = 0; i < 4; i++) {
        float2 lo = make_float2(v[i].x * inv, v[i].y * inv);
        float2 hi = make_float2(v[i].z * inv, v[i].w * inv);
        const uint32_t plo = __nv_cvt_float2_to_fp8x2(lo, __NV_SATFINITE, __NV_E4M3);
        const uint32_t phi = __nv_cvt_float2_to_fp8x2(hi, __NV_SATFINITE, __NV_E4M3);
        packed[i] = (plo & 0xFFFFu) | (phi << 16);
    }
    uint4 u;
    u.x = packed[0]; u.y = packed[1]; u.z = packed[2]; u.w = packed[3];
    *(uint4*)(g_sn8 + (size_t)row * DDIM + tid * 16) = u;
}

// ---------------------------------------------------------------------------
// Fused kernel: blocks [0,136) = FP8 GEMM tiles (+ loss tail + final combine),
// blocks [136,296) = MSE stream. 2 blocks/SM (110.6 KB smem).
// ---------------------------------------------------------------------------
#define LDSS8 144                    // smem row stride bytes (128 + 16 pad)
#define TILE8 (128 * LDSS8)          // 18432 bytes per tile buffer
#define STAGEB (2 * TILE8)           // A+B per stage = 36864
#define STAGES 3
#define SMEM_TC (STAGES * STAGEB)    // 110592 bytes

__device__ __forceinline__ uint32_t smem_u32(const void* p) {
    return (uint32_t)__cvta_generic_to_shared(p);
}

__device__ __forceinline__ void cp_async16(uint32_t s, const void* g) {
    asm volatile("cp.async.cg.shared.global [%0], [%1], 16;\n" :: "r"(s), "l"(g));
}

__device__ __forceinline__ void ldsm4(uint32_t& r0, uint32_t& r1, uint32_t& r2,
                                      uint32_t& r3, uint32_t a) {
    asm volatile("ldmatrix.sync.aligned.m8n8.x4.shared.b16 {%0,%1,%2,%3}, [%4];\n"
                 : "=r"(r0), "=r"(r1), "=r"(r2), "=r"(r3)
                 : "r"(a));
}

__device__ __forceinline__ void mma16832(float c[4], const uint32_t a[4],
                                         const uint32_t b[2]) {
    asm volatile(
        "mma.sync.aligned.m16n8k32.row.col.f32.e4m3.e4m3.f32 "
        "{%0,%1,%2,%3}, {%4,%5,%6,%7}, {%8,%9}, {%0,%1,%2,%3};\n"
        : "+f"(c[0]), "+f"(c[1]), "+f"(c[2]), "+f"(c[3])
        : "r"(a[0]), "r"(a[1]), "r"(a[2]), "r"(a[3]), "r"(b[0]), "r"(b[1]));
}

// Grid barrier among the NB_GEMM gemm blocks (bids 0..135 — all first-wave
// resident, so spinning is deadlock-free). Generation-based: no reset needed.
__device__ __forceinline__ void grid_bar(unsigned* ctr) {
    __threadfence();
    __syncthreads();
    if (threadIdx.x == 0) {
        const unsigned ticket = atomicAdd(ctr, 1u);
        const unsigned target = (ticket / NB_GEMM + 1u) * NB_GEMM;
        while (atomicAdd(ctr, 0u) < target) {}
    }
    __syncthreads();
    __threadfence();
}

__global__ void __launch_bounds__(256, 2) k_gm(const float* __restrict__ pic,
                                               const float* __restrict__ dec,
                                               float* __restrict__ out) {
    extern __shared__ char smem[];
    const int tid = threadIdx.x;
    __shared__ float wred[8];
    __shared__ float wred2[8];
    __shared__ unsigned s_t3;

    if (blockIdx.x >= NB_GEMM) {
        // ---------------- MSE branch ----------------
        const int mb = blockIdx.x - NB_GEMM;
        const int total4 = PIC_ELEMS / 4;
        const int slab4 = SLAB / 4;
        float s = 0.f;
        for (int i4 = mb * 256 + tid; i4 < total4; i4 += NB_MSE * 256) {
            const int n = i4 / slab4;
            const int rem4 = i4 - n * slab4;
            const int di4 = ((n + 1) & 15) * slab4 + rem4;
            const float4 a = *((const float4*)pic + i4);
            const float4 b = *((const float4*)dec + di4);
            const float dx = a.x - b.x, dy = a.y - b.y, dz = a.z - b.z,
                        dw = a.w - b.w;
            s += dx * dx + dy * dy + dz * dz + dw * dw;
        }
        const int lane = tid & 31, warp = tid >> 5;
#pragma unroll
        for (int o = 16; o > 0; o >>= 1) s += __shfl_xor_sync(0xffffffffu, s, o);
        if (lane == 0) wred[warp] = s;
        __syncthreads();
        if (tid == 0) {
            float t = 0.f;
#pragma unroll
            for (int i = 0; i < 8; i++) t += wred[i];
            g_msepart[mb] = t;
            __threadfence();
            atomicAdd(&g_cmse, 1u);
        }
        return;
    }

    // ---------------- GEMM branch ----------------
    const int b = blockIdx.x;
    const int lane = tid & 31, warp = tid >> 5;
    const int wm = warp >> 2, wn = warp & 3;

    // Decode upper-triangular tile index: b in [0,136)
    int bidx = b, tm = 0;
    while (bidx >= 16 - tm) { bidx -= 16 - tm; tm++; }
    const int tn = tm + bidx;
    const int mbase = tm * 128, nbase = tn * 128;

    float acc[4][4][4];
#pragma unroll
    for (int i = 0; i < 4; i++)
#pragma unroll
        for (int j = 0; j < 4; j++)
#pragma unroll
            for (int k = 0; k < 4; k++) acc[i][j][k] = 0.f;

    auto load_chunk = [&](int c, int stg) {
        const uint32_t sa = smem_u32(smem + stg * STAGEB);
        const uint32_t sbm = sa + TILE8;
#pragma unroll
        for (int i = 0; i < 4; i++) {
            const int idx = tid + i * 256;  // 0..1023
            const int row = idx >> 3;       // 0..127
            const int c16 = idx & 7;        // 16B chunk within 128B row
            const uint32_t so = (uint32_t)(row * LDSS8 + c16 * 16);
            cp_async16(sa + so,
                       g_sn8 + (size_t)(mbase + row) * DDIM + (c << 7) + c16 * 16);
            cp_async16(sbm + so,
                       g_sn8 + (size_t)(nbase + row) * DDIM + (c << 7) + c16 * 16);
        }
        asm volatile("cp.async.commit_group;\n" ::: "memory");
    };

    const int a_row_off = ((lane >> 3) & 1) * 8 + (lane & 7);
    const int a_col_off = ((lane >> 4) & 1) * 16;  // bytes
    const int b_grp = lane >> 3;
    const int b_row_off = (b_grp >> 1) * 8 + (lane & 7);
    const int b_col_off = (b_grp & 1) * 16;        // bytes

    load_chunk(0, 0);
    load_chunk(1, 1);

    for (int c = 0; c < 32; c++) {
        const int stg = c % STAGES;
        if (c < 31) {
            asm volatile("cp.async.wait_group 1;\n" ::: "memory");
        } else {
            asm volatile("cp.async.wait_group 0;\n" ::: "memory");
        }
        __syncthreads();
        if (c + 2 < 32) load_chunk(c + 2, (c + 2) % STAGES);

        const char* As = smem + stg * STAGEB;
        const char* Bs = smem + stg * STAGEB + TILE8;
#pragma unroll
        for (int ksb = 0; ksb < 128; ksb += 32) {
            uint32_t a[4][4], bb[4][2];
#pragma unroll
            for (int mi = 0; mi < 4; mi++) {
                const uint32_t ad = smem_u32(
                    As + (wm * 64 + mi * 16 + a_row_off) * LDSS8 + ksb + a_col_off);
                ldsm4(a[mi][0], a[mi][1], a[mi][2], a[mi][3], ad);
            }
#pragma unroll
            for (int nb = 0; nb < 2; nb++) {
                const uint32_t ad = smem_u32(
                    Bs + (wn * 32 + nb * 16 + b_row_off) * LDSS8 + ksb + b_col_off);
                uint32_t r0, r1, r2, r3;
                ldsm4(r0, r1, r2, r3, ad);
                bb[nb * 2][0] = r0;
                bb[nb * 2][1] = r1;
                bb[nb * 2 + 1][0] = r2;
                bb[nb * 2 + 1][1] = r3;
            }
#pragma unroll
            for (int mi = 0; mi < 4; mi++)
#pragma unroll
                for (int ni = 0; ni < 4; ni++) mma16832(acc[mi][ni], a[mi], bb[ni]);
        }
    }
    __syncthreads();

    // ---- Epilogue: exp sums + diagonal capture ----
    const float LGSCALE = 1.f / 2048.f;   // acc holds 4096*sim; logit=acc/2048
    const float SIMSCALE = 1.f / 4096.f;
    float* redbuf = (float*)smem;         // 128 rows x 4 wn-warps
    float* colbuf = (float*)smem + 512;   // 128 cols x 2 wm-warps
    const int quad = lane >> 2, tid4 = lane & 3;

    float cs0[4], cs1[4];
#pragma unroll
    for (int ni = 0; ni < 4; ni++) { cs0[ni] = 0.f; cs1[ni] = 0.f; }

#pragma unroll
    for (int mi = 0; mi < 4; mi++) {
        float s0 = 0.f, s1 = 0.f;
        const int r0l = wm * 64 + mi * 16 + quad;
#pragma unroll
        for (int ni = 0; ni < 4; ni++) {
            const int c0l = wn * 32 + ni * 8 + tid4 * 2;
            const float v0 = acc[mi][ni][0], v1 = acc[mi][ni][1];
            const float v2 = acc[mi][ni][2], v3 = acc[mi][ni][3];
            const float e0 = __expf(LGSCALE * v0), e1 = __expf(LGSCALE * v1);
            const float e2 = __expf(LGSCALE * v2), e3 = __expf(LGSCALE * v3);
            s0 += e0 + e1;
            s1 += e2 + e3;
            cs0[ni] += e0 + e2;
            cs1[ni] += e1 + e3;
            if (r0l == c0l) {
                g_P[(size_t)(mbase + r0l) * 16 + tn] = v0 * SIMSCALE;
                if (tm != tn) g_P[(size_t)(nbase + c0l) * 16 + tm] = v0 * SIMSCALE;
            }
            if (r0l == c0l + 1) {
                g_P[(size_t)(mbase + r0l) * 16 + tn] = v1 * SIMSCALE;
                if (tm != tn) g_P[(size_t)(nbase + c0l + 1) * 16 + tm] = v1 * SIMSCALE;
            }
            if (r0l + 8 == c0l) {
                g_P[(size_t)(mbase + r0l + 8) * 16 + tn] = v2 * SIMSCALE;
                if (tm != tn) g_P[(size_t)(nbase + c0l) * 16 + tm] = v2 * SIMSCALE;
            }
            if (r0l + 8 == c0l + 1) {
                g_P[(size_t)(mbase + r0l + 8) * 16 + tn] = v3 * SIMSCALE;
                if (tm != tn) g_P[(size_t)(nbase + c0l + 1) * 16 + tm] = v3 * SIMSCALE;
            }
        }
        s0 += __shfl_xor_sync(0xffffffffu, s0, 1);
        s0 += __shfl_xor_sync(0xffffffffu, s0, 2);
        s1 += __shfl_xor_sync(0xffffffffu, s1, 1);
        s1 += __shfl_xor_sync(0xffffffffu, s1, 2);
        if (tid4 == 0) {
            redbuf[r0l * 4 + wn] = s0;
            redbuf[(r0l + 8) * 4 + wn] = s1;
        }
    }
#pragma unroll
    for (int ni = 0; ni < 4; ni++) {
#pragma unroll
        for (int o = 4; o < 32; o <<= 1) {
            cs0[ni] += __shfl_xor_sync(0xffffffffu, cs0[ni], o);
            cs1[ni] += __shfl_xor_sync(0xffffffffu, cs1[ni], o);
        }
        if (lane < 4) {
            const int col = wn * 32 + ni * 8 + lane * 2;
            colbuf[col * 2 + wm] = cs0[ni];
            colbuf[(col + 1) * 2 + wm] = cs1[ni];
        }
    }
    __syncthreads();
    if (tid < 128) {
        const float t = redbuf[tid * 4 + 0] + redbuf[tid * 4 + 1] +
                        redbuf[tid * 4 + 2] + redbuf[tid * 4 + 3];
        g_Epart[(size_t)(mbase + tid) * 16 + tn] = t;
        if (tm != tn) {
            const float cst = colbuf[tid * 2 + 0] + colbuf[tid * 2 + 1];
            g_Epart[(size_t)(nbase + tid) * 16 + tm] = cst;
        }
    }

    // ---- Barrier: all Epart/P written (gemm blocks only; all resident) ----
    grid_bar(&g_c2);

    // ---- Loss partials for this block's row slice ----
    const int rbase = b * 15 + (b < 8 ? b : 8);
    const int rcnt = 15 + (b < 8 ? 1 : 0);
    float contrib = 0.f;
    if (tid < rcnt) {
        const int i = rbase + tid;
        const int nrow = i >> 7;
        float4 ep[4], pp[4];
#pragma unroll
        for (int q = 0; q < 4; q++) {
            ep[q] = *((const float4*)(g_Epart + i * 16) + q);
            pp[q] = *((const float4*)(g_P + i * 16) + q);
        }
        const float* epf = (const float*)ep;
        const float* ppf = (const float*)pp;
        float esum = 0.f, esub = 0.f;
        float pv[16], ev[16];
#pragma unroll
        for (int m = 0; m < 16; m++) {
            esum += epf[m];
            pv[m] = 2.f * ppf[m];
            ev[m] = __expf(pv[m]);
            esub += ev[m];
        }
        const float eneg = esum - esub;
#pragma unroll
        for (int m = 0; m < 16; m++)
            if (m != nrow) contrib += __logf(eneg + ev[m]) - pv[m];
    }
    if (tid < 32) {
#pragma unroll
        for (int o = 16; o > 0; o >>= 1)
            contrib += __shfl_xor_sync(0xffffffffu, contrib, o);
        if (tid == 0) g_losspart[b] = contrib;
    }
    __syncthreads();

    // ---- Final combine: last gemm block joins mse and writes out ----
    if (tid == 0) {
        __threadfence();
        s_t3 = atomicAdd(&g_c3, 1u);
    }
    __syncthreads();
    const unsigned t3 = s_t3;
    if ((t3 % NB_GEMM) == NB_GEMM - 1) {
        const unsigned gen = t3 / NB_GEMM;
        if (tid == 0) {
            while (atomicAdd(&g_cmse, 0u) < (gen + 1u) * NB_MSE) {}
            __threadfence();
        }
        __syncthreads();
        float sl = (tid < NB_GEMM) ? g_losspart[tid] : 0.f;
        float sm = (tid < NB_MSE) ? g_msepart[tid] : 0.f;
#pragma unroll
        for (int o = 16; o > 0; o >>= 1) {
            sl += __shfl_xor_sync(0xffffffffu, sl, o);
            sm += __shfl_xor_sync(0xffffffffu, sm, o);
        }
        if (lane == 0) { wred[warp] = sl; wred2[warp] = sm; }
        __syncthreads();
        if (tid == 0) {
            float lt = 0.f, mt = 0.f;
#pragma unroll
            for (int j = 0; j < 8; j++) { lt += wred[j]; mt += wred2[j]; }
            out[0] = mt * (1.f / (float)PIC_ELEMS) +
                     lt * (1.f / (float)(KROWS * 15));
        }
    }
}

// ---------------------------------------------------------------------------
extern "C" void kernel_launch(void* const* d_in, const int* in_sizes, int n_in,
                              void* d_out, int out_size) {
    (void)in_sizes; (void)n_in; (void)out_size;
    const float* pic = (const float*)d_in[0];
    const float* dec = (const float*)d_in[1];
    const float* h   = (const float*)d_in[2];

    // Idempotent host-side attribute set (no device memory, no stream work).
    cudaFuncSetAttribute(k_gm, cudaFuncAttributeMaxDynamicSharedMemorySize,
                         SMEM_TC);

    k_norm<<<KROWS, 256>>>(h);
    k_gm<<<NB_TOTAL, 256, SMEM_TC>>>(pic, dec, (float*)d_out);
}